// round 8
// baseline (speedup 1.0000x reference)
#include <cuda_runtime.h>
#include <cuda_fp16.h>
#include <cstdint>
#include <math.h>

// BatchHardTripletLoss: N=8192, D=128, fp32 in, scalar fp32 out.
// Gram on mma.sync fp16 (fp32 acc), single pass: dot = fp16(x)_i . fp16(x)_j
// Upper-triangle 128x128 tiles (2080); PERSISTENT CTAs (304 = 2/SM), each
// runs ~7 contiguous tiles with a software pipeline:
//   top of tile t: wait B(t), sync, issue prefetch B(t+1) [same strip]
//   k-loop(t) -> sync -> [strip change: restage A+B(t+1)] -> epilogue(t)
// Epilogue col-fold scratch aliases the just-consumed B buffer; the other
// B buffer holds the in-flight prefetch (disjoint).
// Dual fold per tile:
//   row-fold: anchors i, tv = cj[j] - 2 dot -> slot (bj, sub=wn)   [shfl]
//   col-fold: anchors j, tv = cj[i] - 2 dot -> slot (bi, sub=2)    [smem]

#define NPTS   8192
#define DIM    128
#define MARGIN 0.2f
#define EPSV   1e-6f
#define TILE   128
#define NTILES 2080              // 64*65/2
#define NPCTA  304               // 2 per SM
#define NSUB   3

// smem layout (bytes)
#define OFF_A    0               // 32 KB fp16 A tile (per-strip resident)
#define OFF_B0   32768           // 32 KB B buffer 0
#define OFF_B1   65536           // 32 KB B buffer 1
#define OFF_CJR  98304           // float2[128] row meta (cj, label)
#define OFF_CJC0 99328           // float2[128] col meta buf 0
#define OFF_CJC1 100352          // float2[128] col meta buf 1
#define SMEM_BYTES 101376
#define SCR_STRIDE 18            // 16 groups + pad -> conflict-free
#define SCR_HN_OFF (128 * SCR_STRIDE * 4)   // 9216 B (within 32 KB B buffer)

__device__ float g_ci[NPTS];
__device__ float g_cj[NPTS];
__device__ __align__(16) __half g_xh[NPTS * DIM];
__device__ float g_php[64 * NSUB * NPTS];
__device__ float g_phn[64 * NSUB * NPTS];
__device__ float g_bsum[32];
__device__ int   g_cnt = 0;

// ---------------- helpers ----------------
__device__ __forceinline__ uint32_t smem_u32(const void* p) {
    uint32_t a;
    asm("{ .reg .u64 t; cvta.to.shared.u64 t, %1; cvt.u32.u64 %0, t; }" : "=r"(a) : "l"(p));
    return a;
}
// swizzled offset of 16B chunk c (0..15) in row r (0..127), 128x128 f16 tile
__device__ __forceinline__ uint32_t t_off(int r, int c) {
    return (uint32_t)(((r >> 3) << 10) + ((c >> 3) << 14) + ((r & 7) << 7)
                      + (((c & 7) ^ (r & 7)) << 4));
}
__device__ __forceinline__ void cp16(uint32_t saddr, const void* gaddr) {
    asm volatile("cp.async.cg.shared.global [%0], [%1], 16;"
                 :: "r"(saddr), "l"(gaddr) : "memory");
}
__device__ __forceinline__ void ldsm4(uint32_t* r, uint32_t addr) {
    asm volatile("ldmatrix.sync.aligned.m8n8.x4.shared.b16 {%0,%1,%2,%3}, [%4];"
                 : "=r"(r[0]), "=r"(r[1]), "=r"(r[2]), "=r"(r[3]) : "r"(addr));
}
__device__ __forceinline__ void mma16816(float* c, const uint32_t* a, const uint32_t* b) {
    asm volatile("mma.sync.aligned.m16n8k16.row.col.f32.f16.f16.f32 "
                 "{%0,%1,%2,%3}, {%4,%5,%6,%7}, {%8,%9}, {%0,%1,%2,%3};"
                 : "+f"(c[0]), "+f"(c[1]), "+f"(c[2]), "+f"(c[3])
                 : "r"(a[0]), "r"(a[1]), "r"(a[2]), "r"(a[3]), "r"(b[0]), "r"(b[1]));
}
__device__ __forceinline__ int strip_base(int b) { return b * (129 - b) / 2; }
__device__ __forceinline__ void tile_decode(int t, int& bi, int& bj) {
    int b = (int)(64.5f - sqrtf(64.5f * 64.5f - 2.0f * (float)t));
    if (b < 0) b = 0; if (b > 63) b = 63;
    while (b < 63 && strip_base(b + 1) <= t) b++;
    while (b > 0 && strip_base(b) > t) b--;
    bi = b; bj = b + (t - strip_base(b));
}
// stage one 128x128 fp16 tile (32 KB) into swizzled smem
__device__ __forceinline__ void stage_tile(uint32_t dst, const char* g, int tid) {
    #pragma unroll
    for (int it = 0; it < 8; it++) {
        int lin = it * 256 + tid;
        uint32_t off = t_off(lin >> 4, lin & 15);
        cp16(dst + off, g + (size_t)lin * 16);
    }
}

// ---------------- precompute: ci/cj + fp16 conversion (2 rows/warp) ------
__global__ void precompute_kernel(const float* __restrict__ x) {
    int w = (blockIdx.x * blockDim.x + threadIdx.x) >> 5;
    int lane = threadIdx.x & 31;
    int row0 = w * 2;
    float4 v0 = *(const float4*)(x + (size_t)row0 * DIM + lane * 4);
    float4 v1 = *(const float4*)(x + (size_t)(row0 + 1) * DIM + lane * 4);
    #pragma unroll
    for (int r = 0; r < 2; r++) {
        float4 v = r ? v1 : v0;
        int row = row0 + r;
        float sq = v.x * v.x + v.y * v.y + v.z * v.z + v.w * v.w;
        float s  = v.x + v.y + v.z + v.w;
        #pragma unroll
        for (int o = 16; o; o >>= 1) {
            sq += __shfl_xor_sync(0xffffffffu, sq, o);
            s  += __shfl_xor_sync(0xffffffffu, s,  o);
        }
        if (lane == 0) {
            g_ci[row] = sq - 2.0f * EPSV * s;
            g_cj[row] = sq + 2.0f * EPSV * s + (float)DIM * EPSV * EPSV;
        }
        __half2* dh = (__half2*)(g_xh + (size_t)row * DIM + lane * 4);
        dh[0] = __floats2half2_rn(v.x, v.y);
        dh[1] = __floats2half2_rn(v.z, v.w);
    }
}

// ---------------- persistent pipelined tile kernel ----------------
__global__ void __launch_bounds__(256, 2)
tile_kernel(const int* __restrict__ tgt) {
    extern __shared__ char smem[];
    const uint32_t sb = smem_u32(smem);
    const int tid  = threadIdx.x;
    const int lane = tid & 31;
    const int wid  = tid >> 5;
    const int wm = wid & 3;          // 4 warps over M (32 rows each)
    const int wn = wid >> 2;         // 2 warps over N (64 cols each)
    float2* scjr = (float2*)(smem + OFF_CJR);

    // contiguous tile range for this CTA: 256 CTAs x 7, 48 CTAs x 6
    const int c = blockIdx.x;
    const int start = c * 6 + (c < 256 ? c : 256);
    const int cnt   = 6 + (c < 256 ? 1 : 0);

    int bi, bj;
    tile_decode(start, bi, bj);

    // prologue: stage A + B0 + meta
    stage_tile(sb + OFF_A,  (const char*)(g_xh + (size_t)bi * TILE * DIM), tid);
    stage_tile(sb + OFF_B0, (const char*)(g_xh + (size_t)bj * TILE * DIM), tid);
    if (tid < TILE) {
        int r = bi * TILE + tid;
        int j = bj * TILE + tid;
        scjr[tid] = make_float2(g_cj[r], __int_as_float(tgt[r]));
        ((float2*)(smem + OFF_CJC0))[tid] = make_float2(g_cj[j], __int_as_float(tgt[j]));
    }
    asm volatile("cp.async.commit_group;" ::: "memory");

    const int ra_lane = (lane & 15);
    const int ca_add  = (lane >> 4);
    const int rb_lane = ((lane >> 4) << 3) + (lane & 7);
    const int cb_add  = ((lane >> 3) & 1);

    for (int s = 0; s < cnt; s++) {
        const int p = s & 1;
        const uint32_t sBp = sb + (p ? OFF_B1 : OFF_B0);
        const uint32_t sBn = sb + (p ? OFF_B0 : OFF_B1);
        float2* scjc  = (float2*)(smem + (p ? OFF_CJC1 : OFF_CJC0));
        float2* scjcn = (float2*)(smem + (p ? OFF_CJC0 : OFF_CJC1));

        int nbi = -1, nbj = -1;
        if (s + 1 < cnt) tile_decode(start + s + 1, nbi, nbj);

        asm volatile("cp.async.wait_group 0;" ::: "memory");
        __syncthreads();

        // same-strip prefetch of B(t+1) into the other buffer (whole k-loop to land)
        bool pre = false;
        if (nbi == bi) {
            stage_tile(sBn, (const char*)(g_xh + (size_t)nbj * TILE * DIM), tid);
            if (tid < TILE) {
                int j = nbj * TILE + tid;
                scjcn[tid] = make_float2(g_cj[j], __int_as_float(tgt[j]));
            }
            asm volatile("cp.async.commit_group;" ::: "memory");
            pre = true;
        }

        // row meta -> regs (before any possible restage of scjr)
        float cjr[2][2];
        int   tir[2][2];
        #pragma unroll
        for (int mt = 0; mt < 2; mt++)
            #pragma unroll
            for (int so = 0; so < 2; so++) {
                float2 q = scjr[wm * 32 + mt * 16 + so * 8 + (lane >> 2)];
                cjr[mt][so] = q.x;
                tir[mt][so] = __float_as_int(q.y);
            }

        // ---------------- single-pass MMA over K=128 ----------------
        float acc[2][8][4];
        #pragma unroll
        for (int mt = 0; mt < 2; mt++)
            #pragma unroll
            for (int n8 = 0; n8 < 8; n8++)
                #pragma unroll
                for (int q = 0; q < 4; q++) acc[mt][n8][q] = 0.0f;

        #pragma unroll
        for (int ks = 0; ks < 8; ks++) {
            uint32_t ah[2][4], bh[4][4];
            #pragma unroll
            for (int mt = 0; mt < 2; mt++) {
                uint32_t off = t_off(wm * 32 + mt * 16 + ra_lane, 2 * ks + ca_add);
                ldsm4(ah[mt], sb + OFF_A + off);
            }
            #pragma unroll
            for (int nt = 0; nt < 4; nt++) {
                uint32_t off = t_off(wn * 64 + nt * 16 + rb_lane, 2 * ks + cb_add);
                ldsm4(bh[nt], sBp + off);
            }
            #pragma unroll
            for (int mt = 0; mt < 2; mt++)
                #pragma unroll
                for (int nt = 0; nt < 4; nt++) {
                    mma16816(acc[mt][2 * nt],     ah[mt], &bh[nt][0]);
                    mma16816(acc[mt][2 * nt + 1], ah[mt], &bh[nt][2]);
                }
        }

        __syncthreads();   // B[p] + A free for aliasing / restaging

        // strip change: restage A + cjr + B(t+1) + cjc(t+1)
        if (s + 1 < cnt && !pre) {
            stage_tile(sb + OFF_A, (const char*)(g_xh + (size_t)nbi * TILE * DIM), tid);
            stage_tile(sBn, (const char*)(g_xh + (size_t)nbj * TILE * DIM), tid);
            if (tid < TILE) {
                int r = nbi * TILE + tid;
                int j = nbj * TILE + tid;
                scjr[tid] = make_float2(g_cj[r], __int_as_float(tgt[r]));
                scjcn[tid] = make_float2(g_cj[j], __int_as_float(tgt[j]));
            }
            asm volatile("cp.async.commit_group;" ::: "memory");
        }

        // ---------------- dual-fold epilogue (scratch aliases B[p]) ------
        float hpr[2][2], hnr[2][2];
        #pragma unroll
        for (int mt = 0; mt < 2; mt++)
            #pragma unroll
            for (int so = 0; so < 2; so++) { hpr[mt][so] = -3.4e38f; hnr[mt][so] = 3.4e38f; }

        float* scrHp = (float*)sBp;          // via 32-bit smem addr arithmetic below
        // NOTE: sBp is a 32-bit smem address; rebuild generic pointers:
        char* bpc = smem + (p ? OFF_B1 : OFF_B0);
        scrHp = (float*)bpc;
        float* scrHn = (float*)(bpc + SCR_HN_OFF);
        const int g16 = wm * 4 + (lane >> 3);
        const bool keep = ((lane >> 2) & 1) == 0;

        #pragma unroll
        for (int n8 = 0; n8 < 8; n8++) {
            #pragma unroll
            for (int par = 0; par < 2; par++) {
                const int colL = wn * 64 + n8 * 8 + (lane & 3) * 2 + par;
                float2 qc = scjc[colL];
                float cjc = qc.x;
                int   tjc = __float_as_int(qc.y);
                float hpc = -3.4e38f, hnc = 3.4e38f;
                #pragma unroll
                for (int mt = 0; mt < 2; mt++)
                    #pragma unroll
                    for (int so = 0; so < 2; so++) {
                        float d = -2.0f * acc[mt][n8][so * 2 + par];
                        float tvr = d + cjc;
                        float tvc = d + cjr[mt][so];
                        if (tjc == tir[mt][so]) {
                            hpr[mt][so] = fmaxf(hpr[mt][so], tvr);
                            hpc         = fmaxf(hpc,         tvc);
                        } else {
                            hnr[mt][so] = fminf(hnr[mt][so], tvr);
                            hnc         = fminf(hnc,         tvc);
                        }
                    }
                hpc = fmaxf(hpc, __shfl_xor_sync(0xffffffffu, hpc, 4));
                hnc = fminf(hnc, __shfl_xor_sync(0xffffffffu, hnc, 4));
                if (keep) {
                    scrHp[colL * SCR_STRIDE + g16] = hpc;
                    scrHn[colL * SCR_STRIDE + g16] = hnc;
                }
            }
        }

        // row fold across the 4 column-lanes, write slot (bj, sub=wn)
        #pragma unroll
        for (int o = 1; o <= 2; o <<= 1)
            #pragma unroll
            for (int mt = 0; mt < 2; mt++)
                #pragma unroll
                for (int so = 0; so < 2; so++) {
                    hpr[mt][so] = fmaxf(hpr[mt][so], __shfl_xor_sync(0xffffffffu, hpr[mt][so], o));
                    hnr[mt][so] = fminf(hnr[mt][so], __shfl_xor_sync(0xffffffffu, hnr[mt][so], o));
                }
        if ((lane & 3) == 0) {
            #pragma unroll
            for (int mt = 0; mt < 2; mt++)
                #pragma unroll
                for (int so = 0; so < 2; so++) {
                    int r = bi * TILE + wm * 32 + mt * 16 + so * 8 + (lane >> 2);
                    g_php[((bj * NSUB) + wn) * NPTS + r] = hpr[mt][so];
                    g_phn[((bj * NSUB) + wn) * NPTS + r] = hnr[mt][so];
                }
        }

        __syncthreads();   // scratch fully written

        // col fold: tid<128 folds hp for column tid; tid>=128 folds hn
        {
            int colL = tid & 127;
            const float* src = (tid < 128) ? scrHp : scrHn;
            float v = src[colL * SCR_STRIDE];
            if (tid < 128) {
                #pragma unroll
                for (int gq = 1; gq < 16; gq++) v = fmaxf(v, src[colL * SCR_STRIDE + gq]);
                g_php[((bi * NSUB) + 2) * NPTS + bj * TILE + colL] = v;
            } else {
                #pragma unroll
                for (int gq = 1; gq < 16; gq++) v = fminf(v, src[colL * SCR_STRIDE + gq]);
                g_phn[((bi * NSUB) + 2) * NPTS + bj * TILE + colL] = v;
            }
        }

        bi = nbi; bj = nbj;
    }
}

// ---------------- fused merge: slots -> loss -> mean (last block done) ----
__global__ void merge_kernel(float* __restrict__ out) {
    __shared__ float ssum[256];
    __shared__ bool  last;
    int r = blockIdx.x * 256 + threadIdx.x;
    int blk = r >> 7;
    float hp = -3.4e38f, hn = 3.4e38f;
    for (int o = 0; o < 64; o++) {
        const float* php = g_php + (size_t)o * NSUB * NPTS + r;
        const float* phn = g_phn + (size_t)o * NSUB * NPTS + r;
        if (o >= blk) {
            hp = fmaxf(hp, fmaxf(php[0], php[(size_t)NPTS]));
            hn = fminf(hn, fminf(phn[0], phn[(size_t)NPTS]));
        }
        if (o <= blk) {
            hp = fmaxf(hp, php[2 * (size_t)NPTS]);
            hn = fminf(hn, phn[2 * (size_t)NPTS]);
        }
    }
    float ci = g_ci[r];
    float hpd = sqrtf(fmaxf(ci + hp, 0.0f));
    float hnd = sqrtf(fmaxf(ci + hn, 0.0f));
    ssum[threadIdx.x] = fmaxf(hpd - hnd + MARGIN, 0.0f);
    __syncthreads();
    for (int o = 128; o; o >>= 1) {
        if (threadIdx.x < o) ssum[threadIdx.x] += ssum[threadIdx.x + o];
        __syncthreads();
    }
    if (threadIdx.x == 0) {
        g_bsum[blockIdx.x] = ssum[0];
        __threadfence();
        int prev = atomicAdd(&g_cnt, 1);
        last = (prev == gridDim.x - 1);
    }
    __syncthreads();
    if (last && threadIdx.x < 32) {
        float v = g_bsum[threadIdx.x];
        #pragma unroll
        for (int o = 16; o; o >>= 1) v += __shfl_xor_sync(0xffffffffu, v, o);
        if (threadIdx.x == 0) {
            out[0] = v / (float)NPTS;
            g_cnt = 0;   // reset for next graph replay
        }
    }
}

extern "C" void kernel_launch(void* const* d_in, const int* in_sizes, int n_in,
                              void* d_out, int out_size) {
    const float* x   = (const float*)d_in[0];
    const int*   tgt = (const int*)d_in[1];
    float*       out = (float*)d_out;

    precompute_kernel<<<NPTS / 16, 256>>>(x);

    cudaFuncSetAttribute(tile_kernel,
                         cudaFuncAttributeMaxDynamicSharedMemorySize, SMEM_BYTES);
    tile_kernel<<<NPCTA, 256, SMEM_BYTES>>>(tgt);

    merge_kernel<<<NPTS / 256, 256>>>(out);
}